// round 2
// baseline (speedup 1.0000x reference)
#include <cuda_runtime.h>
#include <math.h>

// Problem constants
#define TB   8        // batch
#define TD   512      // D
#define TDD  1024     // 2D
#define TT   4096     // T
#define NCTA 128
#define CJ   8        // h columns per CTA   (TDD / NCTA)
#define CI   4        // p columns per CTA   (TD  / NCTA)
#define NTHR 256
#define NWARP 8

// Persistent scratch (allocation-free rule: __device__ globals)
__device__ float    gMemBuf[2][TB * TD];   // double-buffered recurrent state
__device__ float    gHBuf[2][TB * TDD];    // double-buffered hidden activations
__device__ unsigned gHFlag[NCTA];          // per-CTA progress: h(t) published => t+1
__device__ unsigned gMemFlag[NCTA];        // per-CTA progress: mem(t) published => t+1

__global__ void init_scratch() {
    int t = blockIdx.x * blockDim.x + threadIdx.x;
    if (t < TB * TD) { gMemBuf[0][t] = 0.0f; gMemBuf[1][t] = 0.0f; }
    if (t < NCTA)    { gHFlag[t] = 0u; gMemFlag[t] = 0u; }
}

// packed fp32x2 FMA (Blackwell): 2 MACs per instruction
__device__ __forceinline__ void fma2(unsigned long long& acc,
                                     unsigned long long a,
                                     unsigned long long b) {
    asm volatile("fma.rn.f32x2 %0, %1, %2, %0;" : "+l"(acc) : "l"(a), "l"(b));
}
__device__ __forceinline__ float2 u2f(unsigned long long v) {
    float2 f;
    asm("mov.b64 {%0,%1}, %2;" : "=f"(f.x), "=f"(f.y) : "l"(v));
    return f;
}
// L2-only (L1-bypassing) 16B load — for cross-CTA-produced data
__device__ __forceinline__ ulonglong2 ldg128_cg(const void* p) {
    ulonglong2 v;
    asm volatile("ld.global.cg.v2.u64 {%0,%1}, [%2];"
                 : "=l"(v.x), "=l"(v.y) : "l"(p));
    return v;
}
// read-only cached 16B load — for the immutable x input
__device__ __forceinline__ ulonglong2 ldg128_nc(const void* p) {
    ulonglong2 v;
    asm volatile("ld.global.nc.v2.u64 {%0,%1}, [%2];"
                 : "=l"(v.x), "=l"(v.y) : "l"(p));
    return v;
}
// L2-direct scalar store for cross-CTA data
__device__ __forceinline__ void stg_cg(float* p, float v) {
    asm volatile("st.global.cg.f32 [%0], %1;" :: "l"(p), "f"(v) : "memory");
}
// release flag publish (after __syncthreads: orders whole CTA's prior stores)
__device__ __forceinline__ void flag_release(unsigned* p, unsigned v) {
    asm volatile("st.release.gpu.u32 [%0], %1;" :: "l"(p), "r"(v) : "memory");
}

// Warp-level wait: lanes 0..15 poll 16 consecutive per-CTA flags until all >= tgt.
__device__ __forceinline__ void wait_ge(const unsigned* flagBase, unsigned tgt) {
    const int lane = threadIdx.x & 31;
    const unsigned* p = flagBase + (lane & 15);
    for (;;) {
        unsigned v = tgt;
        if (lane < 16)
            asm volatile("ld.relaxed.gpu.u32 %0, [%1];" : "=r"(v) : "l"(p) : "memory");
        if (__all_sync(0xffffffffu, v >= tgt)) break;
    }
}

__global__ void __launch_bounds__(NTHR, 1)
sys2_kernel(const float* __restrict__ x,
            const float* __restrict__ W1,
            const float* __restrict__ b1,
            const float* __restrict__ W2,
            const float* __restrict__ b2,
            float* __restrict__ y)
{
    extern __shared__ float smem[];
    float* sW1   = smem;                     // CJ*TDD floats (32 KB)
    float* sW2   = sW1 + CJ * TDD;           // CI*TDD floats (16 KB)
    float* sPart = sW2 + CI * TDD;           // NWARP*TB*CJ = 512 floats
    float* sB1   = sPart + NWARP * TB * CJ;  // CJ
    float* sB2   = sB1 + CJ;                 // CI

    const int cta  = blockIdx.x;
    const int tid  = threadIdx.x;
    const int w    = tid >> 5;
    const int lane = tid & 31;
    const int b    = lane >> 2;   // batch owned by this lane
    const int kq   = lane & 3;    // k-phase within 16-wide chunk
    const int jbase = cta * CJ;
    const int ibase = cta * CI;

    // ---- stage this CTA's weight slices into SMEM (once) ----
    {
        const float4* g1 = (const float4*)(W1 + (size_t)jbase * TDD);
        float4* s1 = (float4*)sW1;
        for (int idx = tid; idx < CJ * TDD / 4; idx += NTHR) s1[idx] = g1[idx];
        const float4* g2 = (const float4*)(W2 + (size_t)ibase * TDD);
        float4* s2 = (float4*)sW2;
        for (int idx = tid; idx < CI * TDD / 4; idx += NTHR) s2[idx] = g2[idx];
        if (tid < CJ) sB1[tid] = b1[jbase + tid];
        if (tid < CI) sB2[tid] = b2[ibase + tid];
    }
    __syncthreads();

    // Registered recurrent state for the epilogue threads (tid < 32 owns (bb,ii))
    float memReg = 0.0f;

    // Preload x(0)
    ulonglong2 ex[4];
    {
        const float* xr = x + ((size_t)b * TT + 0) * TD;
#pragma unroll
        for (int it = 0; it < 4; ++it) {
            const int k = (w << 6) + (it << 4) + (kq << 2);
            ex[it] = ldg128_nc(xr + k);
        }
    }

    for (int t = 0; t < TT; ++t) {
        // ===== Phase 1: h = gelu(W1 @ [x_t ; mem(t-1)] + b1), this CTA's j-slice
        if (t > 0) wait_ge(gMemFlag + (w << 4), (unsigned)t);   // mem(t-1) ready (group w)

        const float* mrow = gMemBuf[(t + 1) & 1] + b * TD;      // mem(t-1) lives at parity (t-1)&1
        ulonglong2 em[4];
#pragma unroll
        for (int it = 0; it < 4; ++it) {
            const int k = (w << 6) + (it << 4) + (kq << 2);
            em[it] = ldg128_cg(mrow + k);
        }

        unsigned long long ax[CJ], ay[CJ];
#pragma unroll
        for (int j = 0; j < CJ; ++j) { ax[j] = 0ull; ay[j] = 0ull; }

        // x half (data already in regs — covers the em L2 latency)
#pragma unroll
        for (int it = 0; it < 4; ++it) {
            const int k = (w << 6) + (it << 4) + (kq << 2);
#pragma unroll
            for (int j = 0; j < CJ; ++j) {
                const ulonglong2 wv = *(const ulonglong2*)(sW1 + j * TDD + k);
                fma2(ax[j], wv.x, ex[it].x);
                fma2(ay[j], wv.y, ex[it].y);
            }
        }
        // mem half
#pragma unroll
        for (int it = 0; it < 4; ++it) {
            const int k = (w << 6) + (it << 4) + (kq << 2);
#pragma unroll
            for (int j = 0; j < CJ; ++j) {
                const ulonglong2 wv = *(const ulonglong2*)(sW1 + j * TDD + TD + k);
                fma2(ax[j], wv.x, em[it].x);
                fma2(ay[j], wv.y, em[it].y);
            }
        }
#pragma unroll
        for (int j = 0; j < CJ; ++j) {
            const float2 fx = u2f(ax[j]);
            const float2 fy = u2f(ay[j]);
            float s = (fx.x + fx.y) + (fy.x + fy.y);
            s += __shfl_xor_sync(0xffffffffu, s, 1);
            s += __shfl_xor_sync(0xffffffffu, s, 2);
            if (kq == 0) sPart[(w << 6) + (b << 3) + j] = s;
        }
        __syncthreads();
        if (tid < TB * CJ) {
            const int bb = tid >> 3, jj = tid & 7;
            float s = sB1[jj];
#pragma unroll
            for (int ww = 0; ww < NWARP; ++ww) s += sPart[(ww << 6) + (bb << 3) + jj];
            const float hval = 0.5f * s * (1.0f + erff(s * 0.70710678118654752f));
            stg_cg(&gHBuf[t & 1][bb * TDD + jbase + jj], hval);
        }
        __syncthreads();
        if (tid == 0) flag_release(&gHFlag[cta], (unsigned)(t + 1));

        // ===== Phase 2: p = W2 @ h + b2 ; gated mem update, this CTA's i-slice
        wait_ge(gHFlag + (w << 4), (unsigned)(t + 1));          // h(t) ready (group w)

        const float* hrow = gHBuf[t & 1] + b * TDD;
        ulonglong2 eh[8];
#pragma unroll
        for (int it = 0; it < 8; ++it) {
            const int k = (w << 7) + (it << 4) + (kq << 2);
            eh[it] = ldg128_cg(hrow + k);
        }
        // prefetch x(t+1) while eh is in flight
        {
            const int tn = (t + 1 < TT) ? (t + 1) : t;
            const float* xr = x + ((size_t)b * TT + tn) * TD;
#pragma unroll
            for (int it = 0; it < 4; ++it) {
                const int k = (w << 6) + (it << 4) + (kq << 2);
                ex[it] = ldg128_nc(xr + k);
            }
        }

        unsigned long long px[CI], py[CI];
#pragma unroll
        for (int i = 0; i < CI; ++i) { px[i] = 0ull; py[i] = 0ull; }
#pragma unroll
        for (int it = 0; it < 8; ++it) {
            const int k = (w << 7) + (it << 4) + (kq << 2);
#pragma unroll
            for (int i = 0; i < CI; ++i) {
                const ulonglong2 wv = *(const ulonglong2*)(sW2 + i * TDD + k);
                fma2(px[i], wv.x, eh[it].x);
                fma2(py[i], wv.y, eh[it].y);
            }
        }
#pragma unroll
        for (int i = 0; i < CI; ++i) {
            const float2 fx = u2f(px[i]);
            const float2 fy = u2f(py[i]);
            float s = (fx.x + fx.y) + (fy.x + fy.y);
            s += __shfl_xor_sync(0xffffffffu, s, 1);
            s += __shfl_xor_sync(0xffffffffu, s, 2);
            if (kq == 0) sPart[(w << 5) + (b << 2) + i] = s;
        }
        __syncthreads();
        if (tid < TB * CI) {
            const int bb = tid >> 2, ii = tid & 3;
            float p = sB2[ii];
#pragma unroll
            for (int ww = 0; ww < NWARP; ++ww) p += sPart[(ww << 5) + (bb << 2) + ii];
            const float g = 1.0f / (1.0f + expf(-p));
            memReg = fmaf(p - memReg, g, memReg);        // m*(1-g) + p*g
            stg_cg(&gMemBuf[t & 1][bb * TD + ibase + ii], memReg);
            y[((size_t)bb * TT + t) * TD + ibase + ii] = memReg;
        }
        __syncthreads();
        if (tid == 0) flag_release(&gMemFlag[cta], (unsigned)(t + 1));
    }
}

extern "C" void kernel_launch(void* const* d_in, const int* in_sizes, int n_in,
                              void* d_out, int out_size) {
    const float* x  = (const float*)d_in[0];
    const float* W1 = (const float*)d_in[1];
    const float* b1 = (const float*)d_in[2];
    const float* W2 = (const float*)d_in[3];
    const float* b2 = (const float*)d_in[4];
    float* y = (float*)d_out;

    const size_t SMEM_BYTES =
        (CJ * TDD + CI * TDD + NWARP * TB * CJ + CJ + CI) * sizeof(float);
    cudaFuncSetAttribute(sys2_kernel,
                         cudaFuncAttributeMaxDynamicSharedMemorySize,
                         (int)SMEM_BYTES);

    init_scratch<<<(TB * TD + 255) / 256, 256>>>();
    sys2_kernel<<<NCTA, NTHR, SMEM_BYTES>>>(x, W1, b1, W2, b2, y);
}

// round 3
// speedup vs baseline: 1.1378x; 1.1378x over previous
#include <cuda_runtime.h>
#include <math.h>

#define TB   8
#define TD   512
#define TDD  1024
#define TT   4096
#define NCTA 128
#define CJ   8        // h cols per CTA
#define CI   4        // p cols per CTA
#define NTHR 256
#define NWARP 8

__device__ float    gMem[TB * TD];    // recurrent state (in place; safe, see schedule)
__device__ float    gH[TB * TDD];     // hidden activations (in place)
__device__ unsigned gFlagH[NCTA];     // CTA c released h(t)   => value t+1
__device__ unsigned gFlagM[NCTA];     // CTA c released mem(t) => value t+1

__global__ void init_scratch() {
    int t = blockIdx.x * blockDim.x + threadIdx.x;
    if (t < TB * TD) gMem[t] = 0.0f;
    if (t < NCTA) { gFlagH[t] = 0u; gFlagM[t] = 0u; }
}

__device__ __forceinline__ void fma2(unsigned long long& acc,
                                     unsigned long long a,
                                     unsigned long long b) {
    asm volatile("fma.rn.f32x2 %0, %1, %2, %0;" : "+l"(acc) : "l"(a), "l"(b));
}
__device__ __forceinline__ float2 u2f(unsigned long long v) {
    float2 f;
    asm("mov.b64 {%0,%1}, %2;" : "=f"(f.x), "=f"(f.y) : "l"(v));
    return f;
}
__device__ __forceinline__ ulonglong2 ldg128_cg(const void* p) {
    ulonglong2 v;
    asm volatile("ld.global.cg.v2.u64 {%0,%1}, [%2];"
                 : "=l"(v.x), "=l"(v.y) : "l"(p));
    return v;
}
__device__ __forceinline__ ulonglong2 ldg128_nc(const void* p) {
    ulonglong2 v;
    asm volatile("ld.global.nc.v2.u64 {%0,%1}, [%2];"
                 : "=l"(v.x), "=l"(v.y) : "l"(p));
    return v;
}
__device__ __forceinline__ void stg_cg(float* p, float v) {
    asm volatile("st.global.cg.f32 [%0], %1;" :: "l"(p), "f"(v) : "memory");
}
__device__ __forceinline__ void flag_release(unsigned* p, unsigned v) {
    asm volatile("st.release.gpu.u32 [%0], %1;" :: "l"(p), "r"(v) : "memory");
}
// one warp reads all 128 flags: lane l -> flags[4l..4l+3]
__device__ __forceinline__ uint4 poll_ld(const unsigned* flags) {
    const uint4* p = (const uint4*)flags + (threadIdx.x & 31);
    uint4 v;
    asm volatile("ld.relaxed.gpu.v4.u32 {%0,%1,%2,%3}, [%4];"
                 : "=r"(v.x), "=r"(v.y), "=r"(v.z), "=r"(v.w) : "l"(p) : "memory");
    return v;
}
__device__ __forceinline__ bool poll_ok(uint4 v, unsigned tgt) {
    return __all_sync(0xffffffffu,
                      v.x >= tgt && v.y >= tgt && v.z >= tgt && v.w >= tgt);
}

__global__ void __launch_bounds__(NTHR, 1)
sys2_kernel(const float* __restrict__ x,
            const float* __restrict__ W1,
            const float* __restrict__ b1,
            const float* __restrict__ W2,
            const float* __restrict__ b2,
            float* __restrict__ y)
{
    extern __shared__ float smem[];
    float* sW1   = smem;                     // CJ*TDD (32 KB)
    float* sW2   = sW1 + CJ * TDD;           // CI*TDD (16 KB)
    float* sPart = sW2 + CI * TDD;           // NWARP*TB*CJ = 512
    float* sB1   = sPart + NWARP * TB * CJ;  // CJ
    float* sB2   = sB1 + CJ;                 // CI

    const int cta  = blockIdx.x;
    const int tid  = threadIdx.x;
    const int w    = tid >> 5;
    const int lane = tid & 31;
    const int b    = lane >> 2;   // batch row owned by this lane
    const int kq   = lane & 3;    // k-phase
    const int jbase = cta * CJ;
    const int ibase = cta * CI;

    // stage weight slices to SMEM once
    {
        const float4* g1 = (const float4*)(W1 + (size_t)jbase * TDD);
        float4* s1 = (float4*)sW1;
        for (int idx = tid; idx < CJ * TDD / 4; idx += NTHR) s1[idx] = g1[idx];
        const float4* g2 = (const float4*)(W2 + (size_t)ibase * TDD);
        float4* s2 = (float4*)sW2;
        for (int idx = tid; idx < CI * TDD / 4; idx += NTHR) s2[idx] = g2[idx];
        if (tid < CJ) sB1[tid] = b1[jbase + tid];
        if (tid < CI) sB2[tid] = b2[ibase + tid];
    }
    __syncthreads();

    float memReg = 0.0f;   // recurrent state, owned by tid<32 (bb=tid>>2, ii=tid&3)

    // preload x(0)
    ulonglong2 ex[4];
    {
        const float* xr = x + ((size_t)b * TT) * TD;
#pragma unroll
        for (int it = 0; it < 4; ++it)
            ex[it] = ldg128_nc(xr + (w << 6) + (it << 4) + (kq << 2));
    }

    for (int t = 0; t < TT; ++t) {
        // ========== Phase 1: h = gelu(W1 @ [x_t ; mem] + b1), j-slice ==========
        uint4 pv;
        if (w == 0 && t > 0) pv = poll_ld(gFlagM);   // issue first poll early

        unsigned long long ax[CJ], ay[CJ];
#pragma unroll
        for (int j = 0; j < CJ; ++j) { ax[j] = 0ull; ay[j] = 0ull; }

        // x-half (independent of mem) — hides the poll latency
#pragma unroll
        for (int it = 0; it < 4; ++it) {
            const int k = (w << 6) + (it << 4) + (kq << 2);
#pragma unroll
            for (int j = 0; j < CJ; ++j) {
                const ulonglong2 wv = *(const ulonglong2*)(sW1 + j * TDD + k);
                fma2(ax[j], wv.x, ex[it].x);
                fma2(ay[j], wv.y, ex[it].y);
            }
        }

        if (w == 0 && t > 0) {
            while (!poll_ok(pv, (unsigned)t)) pv = poll_ld(gFlagM);
        }
        __syncthreads();                              // all warps gated on mem ready

        const float* mrow = gMem + b * TD;
        ulonglong2 em[4];
#pragma unroll
        for (int it = 0; it < 4; ++it)
            em[it] = ldg128_cg(mrow + (w << 6) + (it << 4) + (kq << 2));

#pragma unroll
        for (int it = 0; it < 4; ++it) {
            const int k = (w << 6) + (it << 4) + (kq << 2);
#pragma unroll
            for (int j = 0; j < CJ; ++j) {
                const ulonglong2 wv = *(const ulonglong2*)(sW1 + j * TDD + TD + k);
                fma2(ax[j], wv.x, em[it].x);
                fma2(ay[j], wv.y, em[it].y);
            }
        }
#pragma unroll
        for (int j = 0; j < CJ; ++j) {
            const float2 fx = u2f(ax[j]);
            const float2 fy = u2f(ay[j]);
            float s = (fx.x + fx.y) + (fy.x + fy.y);
            s += __shfl_xor_sync(0xffffffffu, s, 1);
            s += __shfl_xor_sync(0xffffffffu, s, 2);
            if (kq == 0) sPart[(w << 6) + (b << 3) + j] = s;
        }
        __syncthreads();
        if (tid < TB * CJ) {
            const int bb = tid >> 3, jj = tid & 7;
            float s = sB1[jj];
#pragma unroll
            for (int ww = 0; ww < NWARP; ++ww) s += sPart[(ww << 6) + (bb << 3) + jj];
            const float hval = 0.5f * s * (1.0f + erff(s * 0.70710678118654752f));
            stg_cg(&gH[bb * TDD + jbase + jj], hval);
        }
        __syncthreads();
        if (tid == 0) flag_release(&gFlagH[cta], (unsigned)(t + 1));

        // ========== Phase 2: p = W2 @ h + b2 ; gated mem update, i-slice ==========
        if (w == 0) pv = poll_ld(gFlagH);             // issue poll early

        // prefetch x(t+1) — independent, hides poll + fills next step
        {
            const int tn = (t + 1 < TT) ? (t + 1) : t;
            const float* xr = x + ((size_t)b * TT + tn) * TD;
#pragma unroll
            for (int it = 0; it < 4; ++it)
                ex[it] = ldg128_nc(xr + (w << 6) + (it << 4) + (kq << 2));
        }

        if (w == 0) {
            while (!poll_ok(pv, (unsigned)(t + 1))) pv = poll_ld(gFlagH);
        }
        __syncthreads();                              // h ready chip-wide

        const float* hrow = gH + b * TDD;
        ulonglong2 eh[8];
#pragma unroll
        for (int it = 0; it < 8; ++it)
            eh[it] = ldg128_cg(hrow + (w << 7) + (it << 4) + (kq << 2));

        unsigned long long px[CI], py[CI];
#pragma unroll
        for (int i = 0; i < CI; ++i) { px[i] = 0ull; py[i] = 0ull; }
#pragma unroll
        for (int it = 0; it < 8; ++it) {
            const int k = (w << 7) + (it << 4) + (kq << 2);
#pragma unroll
            for (int i = 0; i < CI; ++i) {
                const ulonglong2 wv = *(const ulonglong2*)(sW2 + i * TDD + k);
                fma2(px[i], wv.x, eh[it].x);
                fma2(py[i], wv.y, eh[it].y);
            }
        }
#pragma unroll
        for (int i = 0; i < CI; ++i) {
            const float2 fx = u2f(px[i]);
            const float2 fy = u2f(py[i]);
            float s = (fx.x + fx.y) + (fy.x + fy.y);
            s += __shfl_xor_sync(0xffffffffu, s, 1);
            s += __shfl_xor_sync(0xffffffffu, s, 2);
            if (kq == 0) sPart[(w << 5) + (b << 2) + i] = s;
        }
        __syncthreads();
        if (tid < TB * CI) {
            const int bb = tid >> 2, ii = tid & 3;
            float p = sB2[ii];
#pragma unroll
            for (int ww = 0; ww < NWARP; ++ww) p += sPart[(ww << 5) + (bb << 2) + ii];
            const float g = 1.0f / (1.0f + expf(-p));
            memReg = fmaf(p - memReg, g, memReg);     // m*(1-g) + p*g
            stg_cg(&gMem[bb * TD + ibase + ii], memReg);
            y[((size_t)bb * TT + t) * TD + ibase + ii] = memReg;
        }
        __syncthreads();
        if (tid == 0) flag_release(&gFlagM[cta], (unsigned)(t + 1));
    }
}

extern "C" void kernel_launch(void* const* d_in, const int* in_sizes, int n_in,
                              void* d_out, int out_size) {
    const float* x  = (const float*)d_in[0];
    const float* W1 = (const float*)d_in[1];
    const float* b1 = (const float*)d_in[2];
    const float* W2 = (const float*)d_in[3];
    const float* b2 = (const float*)d_in[4];
    float* y = (float*)d_out;

    const size_t SMEM_BYTES =
        (CJ * TDD + CI * TDD + NWARP * TB * CJ + CJ + CI) * sizeof(float);
    cudaFuncSetAttribute(sys2_kernel,
                         cudaFuncAttributeMaxDynamicSharedMemorySize,
                         (int)SMEM_BYTES);

    init_scratch<<<(TB * TD + 255) / 256, 256>>>();
    sys2_kernel<<<NCTA, NTHR, SMEM_BYTES>>>(x, W1, b1, W2, b2, y);
}

// round 4
// speedup vs baseline: 3.4789x; 3.0576x over previous
#include <cuda_runtime.h>
#include <math.h>

#define TB   8
#define TD   512
#define TDD  1024
#define TT   4096
#define NCTA 128
#define CJ   8        // h cols per CTA
#define CI   4        // p cols per CTA
#define NTHR 256
#define NWARP 8

__device__ float gMem[TB * TD];    // recurrent state (in place; schedule-proven safe)
__device__ float gH[TB * TDD];     // hidden activations (in place)
// Two barrier counters on separate L2 lines (monotonic, never reset)
__device__ __align__(256) unsigned gBarH[64];   // arrivals after h(t) published
__device__ __align__(256) unsigned gBarM[64];   // arrivals after mem(t) published

__global__ void init_scratch() {
    int t = blockIdx.x * blockDim.x + threadIdx.x;
    if (t < TB * TD) gMem[t] = 0.0f;
    if (t < 64) { gBarH[t] = 0u; gBarM[t] = 0u; }
}

__device__ __forceinline__ void fma2(unsigned long long& acc,
                                     unsigned long long a,
                                     unsigned long long b) {
    asm volatile("fma.rn.f32x2 %0, %1, %2, %0;" : "+l"(acc) : "l"(a), "l"(b));
}
__device__ __forceinline__ float2 u2f(unsigned long long v) {
    float2 f;
    asm("mov.b64 {%0,%1}, %2;" : "=f"(f.x), "=f"(f.y) : "l"(v));
    return f;
}
__device__ __forceinline__ ulonglong2 ldg128_cg(const void* p) {
    ulonglong2 v;
    asm volatile("ld.global.cg.v2.u64 {%0,%1}, [%2];"
                 : "=l"(v.x), "=l"(v.y) : "l"(p));
    return v;
}
__device__ __forceinline__ ulonglong2 ldg128_nc(const void* p) {
    ulonglong2 v;
    asm volatile("ld.global.nc.v2.u64 {%0,%1}, [%2];"
                 : "=l"(v.x), "=l"(v.y) : "l"(p));
    return v;
}
__device__ __forceinline__ void stg_cg(float* p, float v) {
    asm volatile("st.global.cg.f32 [%0], %1;" :: "l"(p), "f"(v) : "memory");
}
// cumulative-release arrive: publishes all prior CTA stores (after bar.sync)
__device__ __forceinline__ void bar_arrive(unsigned* ctr) {
    unsigned one = 1u;
    asm volatile("red.release.gpu.global.add.u32 [%0], %1;"
                 :: "l"(ctr), "r"(one) : "memory");
}
// single-word, load-latency-paced spin (ONE thread per CTA calls this)
__device__ __forceinline__ void bar_spin(const unsigned* ctr, unsigned tgt) {
    unsigned v;
    do {
        asm volatile("ld.relaxed.gpu.global.u32 %0, [%1];"
                     : "=r"(v) : "l"(ctr) : "memory");
    } while (v < tgt);
}

__global__ void __launch_bounds__(NTHR, 1)
sys2_kernel(const float* __restrict__ x,
            const float* __restrict__ W1,
            const float* __restrict__ b1,
            const float* __restrict__ W2,
            const float* __restrict__ b2,
            float* __restrict__ y)
{
    extern __shared__ float smem[];
    float* sW1   = smem;                     // CJ*TDD (32 KB)
    float* sW2   = sW1 + CJ * TDD;           // CI*TDD (16 KB)
    float* sPart = sW2 + CI * TDD;           // NWARP*TB*CJ = 512
    float* sB1   = sPart + NWARP * TB * CJ;  // CJ
    float* sB2   = sB1 + CJ;                 // CI

    const int cta  = blockIdx.x;
    const int tid  = threadIdx.x;
    const int w    = tid >> 5;
    const int lane = tid & 31;
    const int b    = lane >> 2;
    const int kq   = lane & 3;
    const int jbase = cta * CJ;
    const int ibase = cta * CI;

    {
        const float4* g1 = (const float4*)(W1 + (size_t)jbase * TDD);
        float4* s1 = (float4*)sW1;
        for (int idx = tid; idx < CJ * TDD / 4; idx += NTHR) s1[idx] = g1[idx];
        const float4* g2 = (const float4*)(W2 + (size_t)ibase * TDD);
        float4* s2 = (float4*)sW2;
        for (int idx = tid; idx < CI * TDD / 4; idx += NTHR) s2[idx] = g2[idx];
        if (tid < CJ) sB1[tid] = b1[jbase + tid];
        if (tid < CI) sB2[tid] = b2[ibase + tid];
    }
    __syncthreads();

    float memReg = 0.0f;   // recurrent state owned by tid<32 (bb=tid>>2, ii=tid&3)

    ulonglong2 ex[4];
    {
        const float* xr = x + ((size_t)b * TT) * TD;
#pragma unroll
        for (int it = 0; it < 4; ++it)
            ex[it] = ldg128_nc(xr + (w << 6) + (it << 4) + (kq << 2));
    }

    for (int t = 0; t < TT; ++t) {
        // ===== Phase 1: h = gelu(W1 @ [x_t ; mem] + b1), j-slice =====
        unsigned long long ax[CJ], ay[CJ];
#pragma unroll
        for (int j = 0; j < CJ; ++j) { ax[j] = 0ull; ay[j] = 0ull; }

        // x-half part A (independent of mem) — overlaps the barrier wait
#pragma unroll
        for (int it = 0; it < 2; ++it) {
            const int k = (w << 6) + (it << 4) + (kq << 2);
#pragma unroll
            for (int j = 0; j < CJ; ++j) {
                const ulonglong2 wv = *(const ulonglong2*)(sW1 + j * TDD + k);
                fma2(ax[j], wv.x, ex[it].x);
                fma2(ay[j], wv.y, ex[it].y);
            }
        }

        if (t > 0 && tid == 0) bar_spin(&gBarM[0], (unsigned)t * NCTA);
        __syncthreads();                       // mem(t-1) visible chip-wide

        // issue mem loads, hide their L2 latency under x-half part B
        const float* mrow = gMem + b * TD;
        ulonglong2 em[4];
#pragma unroll
        for (int it = 0; it < 4; ++it)
            em[it] = ldg128_cg(mrow + (w << 6) + (it << 4) + (kq << 2));

#pragma unroll
        for (int it = 2; it < 4; ++it) {
            const int k = (w << 6) + (it << 4) + (kq << 2);
#pragma unroll
            for (int j = 0; j < CJ; ++j) {
                const ulonglong2 wv = *(const ulonglong2*)(sW1 + j * TDD + k);
                fma2(ax[j], wv.x, ex[it].x);
                fma2(ay[j], wv.y, ex[it].y);
            }
        }
#pragma unroll
        for (int it = 0; it < 4; ++it) {
            const int k = (w << 6) + (it << 4) + (kq << 2);
#pragma unroll
            for (int j = 0; j < CJ; ++j) {
                const ulonglong2 wv = *(const ulonglong2*)(sW1 + j * TDD + TD + k);
                fma2(ax[j], wv.x, em[it].x);
                fma2(ay[j], wv.y, em[it].y);
            }
        }
#pragma unroll
        for (int j = 0; j < CJ; ++j) {
            const float2 fx = u2f(ax[j]);
            const float2 fy = u2f(ay[j]);
            float s = (fx.x + fx.y) + (fy.x + fy.y);
            s += __shfl_xor_sync(0xffffffffu, s, 1);
            s += __shfl_xor_sync(0xffffffffu, s, 2);
            if (kq == 0) sPart[(w << 6) + (b << 3) + j] = s;
        }
        __syncthreads();
        if (tid < TB * CJ) {
            const int bb = tid >> 3, jj = tid & 7;
            float s = sB1[jj];
#pragma unroll
            for (int ww = 0; ww < NWARP; ++ww) s += sPart[(ww << 6) + (bb << 3) + jj];
            const float hval = 0.5f * s * (1.0f + erff(s * 0.70710678118654752f));
            stg_cg(&gH[bb * TDD + jbase + jj], hval);
        }
        __syncthreads();
        if (tid == 0) bar_arrive(&gBarH[0]);

        // ===== Phase 2: p = W2 @ h + b2 ; gated mem update, i-slice =====
        // prefetch x(t+1) — overlaps the h-barrier wait
        {
            const int tn = (t + 1 < TT) ? (t + 1) : t;
            const float* xr = x + ((size_t)b * TT + tn) * TD;
#pragma unroll
            for (int it = 0; it < 4; ++it)
                ex[it] = ldg128_nc(xr + (w << 6) + (it << 4) + (kq << 2));
        }

        if (tid == 0) bar_spin(&gBarH[0], (unsigned)(t + 1) * NCTA);
        __syncthreads();                       // h(t) visible chip-wide

        const float* hrow = gH + b * TDD;
        ulonglong2 eh[8];
#pragma unroll
        for (int it = 0; it < 8; ++it)
            eh[it] = ldg128_cg(hrow + (w << 7) + (it << 4) + (kq << 2));

        unsigned long long px[CI], py[CI];
#pragma unroll
        for (int i = 0; i < CI; ++i) { px[i] = 0ull; py[i] = 0ull; }
#pragma unroll
        for (int it = 0; it < 8; ++it) {
            const int k = (w << 7) + (it << 4) + (kq << 2);
#pragma unroll
            for (int i = 0; i < CI; ++i) {
                const ulonglong2 wv = *(const ulonglong2*)(sW2 + i * TDD + k);
                fma2(px[i], wv.x, eh[it].x);
                fma2(py[i], wv.y, eh[it].y);
            }
        }
#pragma unroll
        for (int i = 0; i < CI; ++i) {
            const float2 fx = u2f(px[i]);
            const float2 fy = u2f(py[i]);
            float s = (fx.x + fx.y) + (fy.x + fy.y);
            s += __shfl_xor_sync(0xffffffffu, s, 1);
            s += __shfl_xor_sync(0xffffffffu, s, 2);
            if (kq == 0) sPart[(w << 5) + (b << 2) + i] = s;
        }
        __syncthreads();
        if (tid < TB * CI) {
            const int bb = tid >> 2, ii = tid & 3;
            float p = sB2[ii];
#pragma unroll
            for (int ww = 0; ww < NWARP; ++ww) p += sPart[(ww << 5) + (bb << 2) + ii];
            const float g = 1.0f / (1.0f + expf(-p));
            memReg = fmaf(p - memReg, g, memReg);
            stg_cg(&gMem[bb * TD + ibase + ii], memReg);
            y[((size_t)bb * TT + t) * TD + ibase + ii] = memReg;
        }
        __syncthreads();
        if (tid == 0) bar_arrive(&gBarM[0]);
    }
}

extern "C" void kernel_launch(void* const* d_in, const int* in_sizes, int n_in,
                              void* d_out, int out_size) {
    const float* x  = (const float*)d_in[0];
    const float* W1 = (const float*)d_in[1];
    const float* b1 = (const float*)d_in[2];
    const float* W2 = (const float*)d_in[3];
    const float* b2 = (const float*)d_in[4];
    float* y = (float*)d_out;

    const size_t SMEM_BYTES =
        (CJ * TDD + CI * TDD + NWARP * TB * CJ + CJ + CI) * sizeof(float);
    cudaFuncSetAttribute(sys2_kernel,
                         cudaFuncAttributeMaxDynamicSharedMemorySize,
                         (int)SMEM_BYTES);

    init_scratch<<<(TB * TD + 255) / 256, 256>>>();
    sys2_kernel<<<NCTA, NTHR, SMEM_BYTES>>>(x, W1, b1, W2, b2, y);
}